// round 2
// baseline (speedup 1.0000x reference)
#include <cuda_runtime.h>
#include <math.h>

#define D_MODEL 1024
#define HNUM    16
#define DK      64
#define BSZ     8
#define SEQLEN  1024
#define MTOT    (BSZ * SEQLEN)   // 8192

// Scratch (device globals: allocation-free, graph-safe)
__device__ float g_qh[(size_t)MTOT * D_MODEL];
__device__ float g_kh[(size_t)MTOT * D_MODEL];
__device__ float g_vh[(size_t)MTOT * D_MODEL];
__device__ float g_ctx[(size_t)MTOT * D_MODEL];

// ---------------------------------------------------------------------------
// GEMM: C[M,N] = A[M,K] @ B[K,N] + bias[N]
// M=8192, N=1024, K=1024 (all divisible by tiles; no bounds checks)
// 128x128 block tile, 256 threads, 8x8 microtile, BK=8
// ---------------------------------------------------------------------------
__global__ __launch_bounds__(256) void gemm_bias_kernel(
    const float* __restrict__ A, const float* __restrict__ B,
    const float* __restrict__ bias, float* __restrict__ C)
{
    const int M = MTOT, N = D_MODEL, K = D_MODEL;
    (void)M;
    __shared__ float As[8][128];
    __shared__ float Bs[8][128];

    const int t  = threadIdx.x;
    const int tx = t & 15;        // 0..15 -> N microtile
    const int ty = t >> 4;        // 0..15 -> M microtile
    const int row0 = blockIdx.y * 128;
    const int col0 = blockIdx.x * 128;

    float acc[8][8];
#pragma unroll
    for (int i = 0; i < 8; i++)
#pragma unroll
        for (int j = 0; j < 8; j++) acc[i][j] = 0.0f;

    // A tile load mapping: 128 rows x 8 k-cols = 256 float4
    const int ar = t >> 1;            // 0..127
    const int ac = (t & 1) * 4;       // 0 or 4
    // B tile load mapping: 8 k-rows x 128 cols = 256 float4
    const int br = t >> 5;            // 0..7
    const int bc = (t & 31) * 4;      // 0..124

    const float* Aptr = A + (size_t)(row0 + ar) * K + ac;
    const float* Bptr = B + (size_t)br * N + col0 + bc;

    for (int kt = 0; kt < K; kt += 8) {
        float4 av = *(const float4*)(Aptr + kt);
        float4 bv = *(const float4*)(Bptr + (size_t)kt * N);
        __syncthreads();
        As[ac + 0][ar] = av.x;
        As[ac + 1][ar] = av.y;
        As[ac + 2][ar] = av.z;
        As[ac + 3][ar] = av.w;
        *(float4*)&Bs[br][bc] = bv;
        __syncthreads();
#pragma unroll
        for (int kk = 0; kk < 8; kk++) {
            float a[8], b[8];
            *(float4*)&a[0] = *(const float4*)&As[kk][ty * 8];
            *(float4*)&a[4] = *(const float4*)&As[kk][ty * 8 + 4];
            *(float4*)&b[0] = *(const float4*)&Bs[kk][tx * 8];
            *(float4*)&b[4] = *(const float4*)&Bs[kk][tx * 8 + 4];
#pragma unroll
            for (int i = 0; i < 8; i++)
#pragma unroll
                for (int j = 0; j < 8; j++)
                    acc[i][j] = fmaf(a[i], b[j], acc[i][j]);
        }
    }

    float4 b0 = *(const float4*)(bias + col0 + tx * 8);
    float4 b1 = *(const float4*)(bias + col0 + tx * 8 + 4);
#pragma unroll
    for (int i = 0; i < 8; i++) {
        float* cp = C + (size_t)(row0 + ty * 8 + i) * N + col0 + tx * 8;
        float4 v0 = make_float4(acc[i][0] + b0.x, acc[i][1] + b0.y,
                                acc[i][2] + b0.z, acc[i][3] + b0.w);
        float4 v1 = make_float4(acc[i][4] + b1.x, acc[i][5] + b1.y,
                                acc[i][6] + b1.z, acc[i][7] + b1.w);
        *(float4*)cp       = v0;
        *(float4*)(cp + 4) = v1;
    }
}

// ---------------------------------------------------------------------------
// Flash attention per (b, h, 64-query tile).
// qh/kh/vh stored as [b][s][h][dk] (row stride D_MODEL, head offset h*DK).
// Online softmax, 4x4 register microtile for S and O.
// Dynamic smem: Qst[64][PAD] + Kst[64][PAD] + Vs[64][PAD] + Pst[64][PAD]
// ---------------------------------------------------------------------------
#define PAD 68   // 68*4B row stride: 16B-aligned, bank shift of 4

__global__ __launch_bounds__(256) void attn_kernel(
    const float* __restrict__ qh, const float* __restrict__ kh,
    const float* __restrict__ vh, const int* __restrict__ mask,
    float* __restrict__ ctx)
{
    extern __shared__ float sm[];
    float* Qst = sm;                 // [dk][r]  (Q^T, pre-scaled by 1/8)
    float* Kst = sm + 64 * PAD;      // [dk][c]  (K^T)
    float* Vs  = sm + 2 * 64 * PAD;  // [kc][dk]
    float* Pst = sm + 3 * 64 * PAD;  // [kc][r]  (P^T)

    const int t  = threadIdx.x;
    const int tx = t & 15;           // col group (k-cols for S, dk-cols for O)
    const int ty = t >> 4;           // row group (query rows)
    const int q0 = blockIdx.x * 64;
    const int h  = blockIdx.y;
    const int b  = blockIdx.z;

    const size_t bh_off = (size_t)b * SEQLEN * D_MODEL + (size_t)h * DK;

    // Load Q tile transposed + scaled
    {
        const int r   = t >> 2;           // 0..63 query row
        const int seg = (t & 3) * 16;     // 0,16,32,48
        const float4* qp = (const float4*)(qh + bh_off + (size_t)(q0 + r) * D_MODEL + seg);
#pragma unroll
        for (int c4 = 0; c4 < 4; c4++) {
            float4 v = qp[c4];
            Qst[(seg + c4 * 4 + 0) * PAD + r] = v.x * 0.125f;
            Qst[(seg + c4 * 4 + 1) * PAD + r] = v.y * 0.125f;
            Qst[(seg + c4 * 4 + 2) * PAD + r] = v.z * 0.125f;
            Qst[(seg + c4 * 4 + 3) * PAD + r] = v.w * 0.125f;
        }
    }

    float m_r[4], l_r[4], o[4][4];
#pragma unroll
    for (int i = 0; i < 4; i++) {
        m_r[i] = -1e30f;
        l_r[i] = 0.0f;
#pragma unroll
        for (int j = 0; j < 4; j++) o[i][j] = 0.0f;
    }

    for (int kt = 0; kt < SEQLEN / 64; kt++) {
        const int k0 = kt * 64;
        __syncthreads();   // previous tile's Vs/Pst consumers done (also covers Qst on iter 0)
        // Load K transposed, V direct
        {
            const int r   = t >> 2;
            const int seg = (t & 3) * 16;
            const float4* kp = (const float4*)(kh + bh_off + (size_t)(k0 + r) * D_MODEL + seg);
            const float4* vp = (const float4*)(vh + bh_off + (size_t)(k0 + r) * D_MODEL + seg);
#pragma unroll
            for (int c4 = 0; c4 < 4; c4++) {
                float4 kv = kp[c4];
                Kst[(seg + c4 * 4 + 0) * PAD + r] = kv.x;
                Kst[(seg + c4 * 4 + 1) * PAD + r] = kv.y;
                Kst[(seg + c4 * 4 + 2) * PAD + r] = kv.z;
                Kst[(seg + c4 * 4 + 3) * PAD + r] = kv.w;
                *(float4*)&Vs[r * PAD + seg + c4 * 4] = vp[c4];
            }
        }
        __syncthreads();

        // S = (Q/8) @ K^T : rows q0+ty*4+i, cols k0+tx*4+j
        float s[4][4];
#pragma unroll
        for (int i = 0; i < 4; i++)
#pragma unroll
            for (int j = 0; j < 4; j++) s[i][j] = 0.0f;
#pragma unroll
        for (int kk = 0; kk < 64; kk++) {
            float a[4], bb[4];
            *(float4*)a  = *(const float4*)&Qst[kk * PAD + ty * 4];
            *(float4*)bb = *(const float4*)&Kst[kk * PAD + tx * 4];
#pragma unroll
            for (int i = 0; i < 4; i++)
#pragma unroll
                for (int j = 0; j < 4; j++)
                    s[i][j] = fmaf(a[i], bb[j], s[i][j]);
        }

        // Apply mask (mask==0 -> -1e9, matching reference)
        {
            const int* mbase = mask + ((size_t)b * SEQLEN + q0 + ty * 4) * SEQLEN + k0 + tx * 4;
#pragma unroll
            for (int i = 0; i < 4; i++) {
                int4 mv = *(const int4*)(mbase + (size_t)i * SEQLEN);
                if (mv.x == 0) s[i][0] = -1e9f;
                if (mv.y == 0) s[i][1] = -1e9f;
                if (mv.z == 0) s[i][2] = -1e9f;
                if (mv.w == 0) s[i][3] = -1e9f;
            }
        }

        // Online softmax (row = 16 lanes sharing same ty; xor 1,2,4,8 stays in group)
#pragma unroll
        for (int i = 0; i < 4; i++) {
            float mt = fmaxf(fmaxf(s[i][0], s[i][1]), fmaxf(s[i][2], s[i][3]));
            mt = fmaxf(mt, __shfl_xor_sync(0xffffffffu, mt, 1));
            mt = fmaxf(mt, __shfl_xor_sync(0xffffffffu, mt, 2));
            mt = fmaxf(mt, __shfl_xor_sync(0xffffffffu, mt, 4));
            mt = fmaxf(mt, __shfl_xor_sync(0xffffffffu, mt, 8));
            float mnew  = fmaxf(m_r[i], mt);
            float alpha = __expf(m_r[i] - mnew);
            m_r[i] = mnew;
            float ls = 0.0f;
#pragma unroll
            for (int j = 0; j < 4; j++) {
                s[i][j] = __expf(s[i][j] - mnew);
                ls += s[i][j];
            }
            ls += __shfl_xor_sync(0xffffffffu, ls, 1);
            ls += __shfl_xor_sync(0xffffffffu, ls, 2);
            ls += __shfl_xor_sync(0xffffffffu, ls, 4);
            ls += __shfl_xor_sync(0xffffffffu, ls, 8);
            l_r[i] = l_r[i] * alpha + ls;
#pragma unroll
            for (int j = 0; j < 4; j++) o[i][j] *= alpha;
        }

        // Write P transposed
#pragma unroll
        for (int i = 0; i < 4; i++)
#pragma unroll
            for (int j = 0; j < 4; j++)
                Pst[(tx * 4 + j) * PAD + ty * 4 + i] = s[i][j];
        __syncthreads();

        // O += P @ V : rows ty*4+i, dk cols tx*4+j
#pragma unroll
        for (int kc = 0; kc < 64; kc++) {
            float a[4], bb[4];
            *(float4*)a  = *(const float4*)&Pst[kc * PAD + ty * 4];
            *(float4*)bb = *(const float4*)&Vs[kc * PAD + tx * 4];
#pragma unroll
            for (int i = 0; i < 4; i++)
#pragma unroll
                for (int j = 0; j < 4; j++)
                    o[i][j] = fmaf(a[i], bb[j], o[i][j]);
        }
    }

    // Normalize + write ctx in concat layout [b][s][h*64+dk]
#pragma unroll
    for (int i = 0; i < 4; i++) {
        float inv = 1.0f / l_r[i];
        float4 ov = make_float4(o[i][0] * inv, o[i][1] * inv,
                                o[i][2] * inv, o[i][3] * inv);
        *(float4*)&ctx[((size_t)b * SEQLEN + q0 + ty * 4 + i) * D_MODEL + h * DK + tx * 4] = ov;
    }
}

// ---------------------------------------------------------------------------
// Launch
// ---------------------------------------------------------------------------
extern "C" void kernel_launch(void* const* d_in, const int* in_sizes, int n_in,
                              void* d_out, int out_size)
{
    (void)in_sizes; (void)n_in; (void)out_size;
    const float* q    = (const float*)d_in[0];
    const float* k    = (const float*)d_in[1];
    const float* v    = (const float*)d_in[2];
    const int*   mask = (const int*)d_in[3];
    const float* Wq   = (const float*)d_in[4];
    const float* bq   = (const float*)d_in[5];
    const float* Wk   = (const float*)d_in[6];
    const float* bk   = (const float*)d_in[7];
    const float* Wv   = (const float*)d_in[8];
    const float* bv   = (const float*)d_in[9];
    const float* Wo   = (const float*)d_in[10];
    const float* bo   = (const float*)d_in[11];
    float* out = (float*)d_out;

    float *qh, *kh, *vh, *ctx;
    cudaGetSymbolAddress((void**)&qh,  g_qh);
    cudaGetSymbolAddress((void**)&kh,  g_kh);
    cudaGetSymbolAddress((void**)&vh,  g_vh);
    cudaGetSymbolAddress((void**)&ctx, g_ctx);

    dim3 gemm_grid(D_MODEL / 128, MTOT / 128);   // (8, 64)
    gemm_bias_kernel<<<gemm_grid, 256>>>(q, Wq, bq, qh);
    gemm_bias_kernel<<<gemm_grid, 256>>>(k, Wk, bk, kh);
    gemm_bias_kernel<<<gemm_grid, 256>>>(v, Wv, bv, vh);

    const int attn_smem = 4 * 64 * PAD * (int)sizeof(float);  // 69632 B
    static bool attr_set = false;
    if (!attr_set) {
        cudaFuncSetAttribute(attn_kernel,
                             cudaFuncAttributeMaxDynamicSharedMemorySize, attn_smem);
        attr_set = true;
    }
    dim3 attn_grid(SEQLEN / 64, HNUM, BSZ);      // (16, 16, 8)
    attn_kernel<<<attn_grid, 256, attn_smem>>>(qh, kh, vh, mask, ctx);

    gemm_bias_kernel<<<gemm_grid, 256>>>(ctx, Wo, bo, out);
}

// round 6
// speedup vs baseline: 1.4610x; 1.4610x over previous
#include <cuda_runtime.h>
#include <cuda_bf16.h>
#include <math.h>
#include <stdint.h>

#define D_MODEL 1024
#define HNUM    16
#define DK      64
#define BSZ     8
#define SEQLEN  1024
#define MTOT    (BSZ * SEQLEN)   // 8192

// ---------------------------------------------------------------------------
// Scratch (device globals: allocation-free, graph-safe)
// ---------------------------------------------------------------------------
__device__ float g_qh[(size_t)MTOT * D_MODEL];
__device__ float g_kh[(size_t)MTOT * D_MODEL];
__device__ float g_vh[(size_t)MTOT * D_MODEL];
__device__ float g_ctx[(size_t)MTOT * D_MODEL];
__device__ unsigned short g_ah[(size_t)MTOT * D_MODEL];   // A hi bf16 [M,K]
__device__ unsigned short g_al[(size_t)MTOT * D_MODEL];   // A lo bf16 [M,K]
__device__ unsigned short g_bth[(size_t)D_MODEL * D_MODEL]; // W^T hi [N,K]
__device__ unsigned short g_btl[(size_t)D_MODEL * D_MODEL]; // W^T lo [N,K]

// ---------------------------------------------------------------------------
// PTX helpers (compute_103-safe: mma.sync / ldmatrix / cp.async only)
// ---------------------------------------------------------------------------
__device__ __forceinline__ uint32_t smem_u32(const void* p) {
    uint32_t a;
    asm("{ .reg .u64 tmp; cvta.to.shared.u64 tmp, %1; cvt.u32.u64 %0, tmp; }"
        : "=r"(a) : "l"(p));
    return a;
}
__device__ __forceinline__ void cp16(uint32_t s, const void* g) {
    asm volatile("cp.async.cg.shared.global [%0], [%1], 16;" :: "r"(s), "l"(g));
}
__device__ __forceinline__ void cp_commit() {
    asm volatile("cp.async.commit_group;");
}
template <int N>
__device__ __forceinline__ void cp_wait() {
    asm volatile("cp.async.wait_group %0;" :: "n"(N) : "memory");
}
__device__ __forceinline__ void ldm_x4(uint32_t* r, uint32_t addr) {
    asm volatile("ldmatrix.sync.aligned.m8n8.x4.shared.b16 {%0,%1,%2,%3}, [%4];"
                 : "=r"(r[0]), "=r"(r[1]), "=r"(r[2]), "=r"(r[3]) : "r"(addr));
}
__device__ __forceinline__ void mma16816(float* c, const uint32_t* a, const uint32_t* b) {
    asm volatile("mma.sync.aligned.m16n8k16.row.col.f32.bf16.bf16.f32 "
                 "{%0,%1,%2,%3}, {%4,%5,%6,%7}, {%8,%9}, {%0,%1,%2,%3};"
                 : "+f"(c[0]), "+f"(c[1]), "+f"(c[2]), "+f"(c[3])
                 : "r"(a[0]), "r"(a[1]), "r"(a[2]), "r"(a[3]),
                   "r"(b[0]), "r"(b[1]));
}

// ---------------------------------------------------------------------------
// Conversion kernels: fp32 -> bf16 hi/lo split
// ---------------------------------------------------------------------------
__global__ __launch_bounds__(256) void conv_hilo_kernel(
    const float4* __restrict__ x, uint2* __restrict__ hi, uint2* __restrict__ lo)
{
    int i = blockIdx.x * 256 + threadIdx.x;
    float4 v = x[i];
    float f[4] = {v.x, v.y, v.z, v.w};
    unsigned int hs[4], ls[4];
#pragma unroll
    for (int j = 0; j < 4; j++) {
        __nv_bfloat16 h = __float2bfloat16_rn(f[j]);
        float r = f[j] - __bfloat162float(h);
        __nv_bfloat16 l = __float2bfloat16_rn(r);
        hs[j] = __bfloat16_as_ushort(h);
        ls[j] = __bfloat16_as_ushort(l);
    }
    hi[i] = make_uint2(hs[0] | (hs[1] << 16), hs[2] | (hs[3] << 16));
    lo[i] = make_uint2(ls[0] | (ls[1] << 16), ls[2] | (ls[3] << 16));
}

// W [K,N] fp32 -> W^T hi/lo bf16 [N,K]
__global__ __launch_bounds__(256) void conv_bt_kernel(
    const float* __restrict__ W, unsigned short* __restrict__ th,
    unsigned short* __restrict__ tl)
{
    __shared__ float t[32][33];
    int n0 = blockIdx.x * 32, k0 = blockIdx.y * 32;
    int tx = threadIdx.x, ty = threadIdx.y;   // block (32, 8)
#pragma unroll
    for (int i = 0; i < 4; i++) {
        int r = ty + i * 8;
        t[r][tx] = W[(size_t)(k0 + r) * D_MODEL + n0 + tx];
    }
    __syncthreads();
#pragma unroll
    for (int i = 0; i < 4; i++) {
        int r = ty + i * 8;
        float f = t[tx][r];
        __nv_bfloat16 h = __float2bfloat16_rn(f);
        float rr = f - __bfloat162float(h);
        __nv_bfloat16 l = __float2bfloat16_rn(rr);
        size_t off = (size_t)(n0 + r) * D_MODEL + k0 + tx;
        th[off] = __bfloat16_as_ushort(h);
        tl[off] = __bfloat16_as_ushort(l);
    }
}

// ---------------------------------------------------------------------------
// HMMA GEMM: C[M,N] = Ah@Bh^T + Ah@Bl^T + Al@Bh^T + bias
// A: [M,K] bf16 row-major; B: [N,K] bf16 row-major (= W^T)
// CTA 128x128, 8 warps (4m x 2n), warp tile 32x64, BK=32, cp.async 2-stage
// ---------------------------------------------------------------------------
#define BK        32
#define ROWS_ELEM 40                 // BK + 8 pad (80 bytes/row, conflict-free)
#define MAT_BYTES (128 * ROWS_ELEM * 2)   // 10240
#define STAGE_BYTES (4 * MAT_BYTES)       // 40960
#define SM_BIAS   0
#define SM_TILES  512
#define G_SMEM_TOTAL (SM_TILES + 2 * STAGE_BYTES)   // 82432

__global__ __launch_bounds__(256, 1)
void gemm_tc_kernel(const unsigned short* __restrict__ Ah,
                    const unsigned short* __restrict__ Al,
                    const unsigned short* __restrict__ Bh,
                    const unsigned short* __restrict__ Bl,
                    const float* __restrict__ bias,
                    float* __restrict__ C)
{
    extern __shared__ char smem[];
    const uint32_t sb = smem_u32(smem);
    const int t    = threadIdx.x;
    const int wid  = t >> 5;
    const int lane = t & 31;
    const int wm   = wid & 3;          // 0..3 -> 32-row band
    const int wn   = wid >> 2;         // 0..1 -> 64-col band
    const int col0 = blockIdx.x * 128;
    const int row0 = blockIdx.y * 128;

    float* sBias = (float*)(smem + SM_BIAS);
    if (t < 128) sBias[t] = bias[col0 + t];

    // chunk loader: Ah/Al rows [row0..+127], Bh/Bl rows [col0..+127], BK=32 cols
    auto load_chunk = [&](int c, int s) {
        const uint32_t base = sb + SM_TILES + s * STAGE_BYTES;
        const size_t koff = (size_t)c * BK * 2;   // bytes along K
#pragma unroll
        for (int i = 0; i < 8; i++) {
            int u = i * 256 + t;
            int mat = u >> 9;          // 0:Ah 1:Al 2:Bh 3:Bl (const per i)
            int v = u & 511;
            int r = v >> 2, j = v & 3;
            uint32_t sa = base + mat * MAT_BYTES + r * (ROWS_ELEM * 2) + j * 16;
            const unsigned short* gp = (mat == 0) ? Ah : (mat == 1) ? Al
                                        : (mat == 2) ? Bh : Bl;
            int grow = ((mat < 2) ? row0 : col0) + r;
            cp16(sa, (const char*)gp + (size_t)grow * (D_MODEL * 2) + koff + j * 16);
        }
    };

    float acc[2][8][4];
#pragma unroll
    for (int mt = 0; mt < 2; mt++)
#pragma unroll
        for (int nt = 0; nt < 8; nt++)
#pragma unroll
            for (int i = 0; i < 4; i++) acc[mt][nt][i] = 0.0f;

    load_chunk(0, 0); cp_commit();
    load_chunk(1, 1); cp_commit();

    // ldmatrix lane address components
    const int sub = lane >> 3;         // 0..3
    const int rin = lane & 7;
    // A: sub&1 -> +8 rows, sub>>1 -> +8 k
    const int a_row_off = (sub & 1) * 8 + rin;
    const int a_col_off = (sub >> 1) * 8;
    // B (pairs of n-tiles): sub>>1 -> n-tile+1, sub&1 -> +8 k
    const int b_nrow_off = (sub >> 1) * 8 + rin;
    const int b_col_off = (sub & 1) * 8;

    const int n_chunks = D_MODEL / BK;   // 32
    for (int c = 0; c < n_chunks; c++) {
        if (c < n_chunks - 1) cp_wait<1>(); else cp_wait<0>();
        __syncthreads();

        const uint32_t stg  = sb + SM_TILES + (c & 1) * STAGE_BYTES;
        const uint32_t stAh = stg;
        const uint32_t stAl = stg + MAT_BYTES;
        const uint32_t stBh = stg + 2 * MAT_BYTES;
        const uint32_t stBl = stg + 3 * MAT_BYTES;

#pragma unroll
        for (int ks = 0; ks < 2; ks++) {
            uint32_t Afh[2][4], Afl[2][4];
#pragma unroll
            for (int mt = 0; mt < 2; mt++) {
                int row = wm * 32 + mt * 16 + a_row_off;
                int colk = ks * 16 + a_col_off;
                uint32_t off = (uint32_t)(row * ROWS_ELEM + colk) * 2;
                ldm_x4(Afh[mt], stAh + off);
                ldm_x4(Afl[mt], stAl + off);
            }
            uint32_t Bfh[8][2], Bfl[8][2];
#pragma unroll
            for (int p = 0; p < 4; p++) {
                int nrow = wn * 64 + p * 16 + b_nrow_off;
                int colk = ks * 16 + b_col_off;
                uint32_t off = (uint32_t)(nrow * ROWS_ELEM + colk) * 2;
                uint32_t tmp[4];
                ldm_x4(tmp, stBh + off);
                Bfh[2 * p][0] = tmp[0]; Bfh[2 * p][1] = tmp[1];
                Bfh[2 * p + 1][0] = tmp[2]; Bfh[2 * p + 1][1] = tmp[3];
                ldm_x4(tmp, stBl + off);
                Bfl[2 * p][0] = tmp[0]; Bfl[2 * p][1] = tmp[1];
                Bfl[2 * p + 1][0] = tmp[2]; Bfl[2 * p + 1][1] = tmp[3];
            }
#pragma unroll
            for (int mt = 0; mt < 2; mt++)
#pragma unroll
                for (int nt = 0; nt < 8; nt++) {
                    mma16816(acc[mt][nt], Afh[mt], Bfh[nt]);
                    mma16816(acc[mt][nt], Afh[mt], Bfl[nt]);
                    mma16816(acc[mt][nt], Afl[mt], Bfh[nt]);
                }
        }

        __syncthreads();
        if (c + 2 < n_chunks) { load_chunk(c + 2, c & 1); cp_commit(); }
    }

    // Epilogue: acc -> C + bias
    const int g   = lane >> 2;
    const int tig = lane & 3;
#pragma unroll
    for (int mt = 0; mt < 2; mt++) {
        int r0 = row0 + wm * 32 + mt * 16 + g;
        int r1 = r0 + 8;
#pragma unroll
        for (int nt = 0; nt < 8; nt++) {
            int lc = wn * 64 + nt * 8 + 2 * tig;
            float bx = sBias[lc], by = sBias[lc + 1];
            float2 v0 = make_float2(acc[mt][nt][0] + bx, acc[mt][nt][1] + by);
            float2 v1 = make_float2(acc[mt][nt][2] + bx, acc[mt][nt][3] + by);
            *(float2*)(C + (size_t)r0 * D_MODEL + col0 + lc) = v0;
            *(float2*)(C + (size_t)r1 * D_MODEL + col0 + lc) = v1;
        }
    }
}

// ---------------------------------------------------------------------------
// Flash attention per (b, h, 64-query tile) — unchanged (passing, L1-bound)
// ---------------------------------------------------------------------------
#define PAD 68

__global__ __launch_bounds__(256) void attn_kernel(
    const float* __restrict__ qh, const float* __restrict__ kh,
    const float* __restrict__ vh, const int* __restrict__ mask,
    float* __restrict__ ctx)
{
    extern __shared__ float sm[];
    float* Qst = sm;
    float* Kst = sm + 64 * PAD;
    float* Vs  = sm + 2 * 64 * PAD;
    float* Pst = sm + 3 * 64 * PAD;

    const int t  = threadIdx.x;
    const int tx = t & 15;
    const int ty = t >> 4;
    const int q0 = blockIdx.x * 64;
    const int h  = blockIdx.y;
    const int b  = blockIdx.z;

    const size_t bh_off = (size_t)b * SEQLEN * D_MODEL + (size_t)h * DK;

    {
        const int r   = t >> 2;
        const int seg = (t & 3) * 16;
        const float4* qp = (const float4*)(qh + bh_off + (size_t)(q0 + r) * D_MODEL + seg);
#pragma unroll
        for (int c4 = 0; c4 < 4; c4++) {
            float4 v = qp[c4];
            Qst[(seg + c4 * 4 + 0) * PAD + r] = v.x * 0.125f;
            Qst[(seg + c4 * 4 + 1) * PAD + r] = v.y * 0.125f;
            Qst[(seg + c4 * 4 + 2) * PAD + r] = v.z * 0.125f;
            Qst[(seg + c4 * 4 + 3) * PAD + r] = v.w * 0.125f;
        }
    }

    float m_r[4], l_r[4], o[4][4];
#pragma unroll
    for (int i = 0; i < 4; i++) {
        m_r[i] = -1e30f;
        l_r[i] = 0.0f;
#pragma unroll
        for (int j = 0; j < 4; j++) o[i][j] = 0.0f;
    }

    for (int kt = 0; kt < SEQLEN / 64; kt++) {
        const int k0 = kt * 64;
        __syncthreads();
        {
            const int r   = t >> 2;
            const int seg = (t & 3) * 16;
            const float4* kp = (const float4*)(kh + bh_off + (size_t)(k0 + r) * D_MODEL + seg);
            const float4* vp = (const float4*)(vh + bh_off + (size_t)(k0 + r) * D_MODEL + seg);
#pragma unroll
            for (int c4 = 0; c4 < 4; c4++) {
                float4 kv = kp[c4];
                Kst[(seg + c4 * 4 + 0) * PAD + r] = kv.x;
                Kst[(seg + c4 * 4 + 1) * PAD + r] = kv.y;
                Kst[(seg + c4 * 4 + 2) * PAD + r] = kv.z;
                Kst[(seg + c4 * 4 + 3) * PAD + r] = kv.w;
                *(float4*)&Vs[r * PAD + seg + c4 * 4] = vp[c4];
            }
        }
        __syncthreads();

        float s[4][4];
#pragma unroll
        for (int i = 0; i < 4; i++)
#pragma unroll
            for (int j = 0; j < 4; j++) s[i][j] = 0.0f;
#pragma unroll
        for (int kk = 0; kk < 64; kk++) {
            float a[4], bb[4];
            *(float4*)a  = *(const float4*)&Qst[kk * PAD + ty * 4];
            *(float4*)bb = *(const float4*)&Kst[kk * PAD + tx * 4];
#pragma unroll
            for (int i = 0; i < 4; i++)
#pragma unroll
                for (int j = 0; j < 4; j++)
                    s[i][j] = fmaf(a[i], bb[j], s[i][j]);
        }

        {
            const int* mbase = mask + ((size_t)b * SEQLEN + q0 + ty * 4) * SEQLEN + k0 + tx * 4;
#pragma unroll
            for (int i = 0; i < 4; i++) {
                int4 mv = *(const int4*)(mbase + (size_t)i * SEQLEN);
                if (mv.x == 0) s[i][0] = -1e9f;
                if (mv.y == 0) s[i][1] = -1e9f;
                if (mv.z == 0) s[i][2] = -1e9f;
                if (mv.w == 0) s[i][3] = -1e9f;
            }
        }

#pragma unroll
        for (int i = 0; i < 4; i++) {
            float mt = fmaxf(fmaxf(s[i][0], s[i][1]), fmaxf(s[i][2], s[i][3]));
            mt = fmaxf(mt, __shfl_xor_sync(0xffffffffu, mt, 1));
            mt = fmaxf(mt, __shfl_xor_sync(0xffffffffu, mt, 2));
            mt = fmaxf(mt, __shfl_xor_sync(0xffffffffu, mt, 4));
            mt = fmaxf(mt, __shfl_xor_sync(0xffffffffu, mt, 8));
            float mnew  = fmaxf(m_r[i], mt);
            float alpha = __expf(m_r[i] - mnew);
            m_r[i] = mnew;
            float ls = 0.0f;
#pragma unroll
            for (int j = 0; j < 4; j++) {
                s[i][j] = __expf(s[i][j] - mnew);
                ls += s[i][j];
            }
            ls += __shfl_xor_sync(0xffffffffu, ls, 1);
            ls += __shfl_xor_sync(0xffffffffu, ls, 2);
            ls += __shfl_xor_sync(0xffffffffu, ls, 4);
            ls += __shfl_xor_sync(0xffffffffu, ls, 8);
            l_r[i] = l_r[i] * alpha + ls;
#pragma unroll
            for (int j = 0; j < 4; j++) o[i][j] *= alpha;
        }

#pragma unroll
        for (int i = 0; i < 4; i++)
#pragma unroll
            for (int j = 0; j < 4; j++)
                Pst[(tx * 4 + j) * PAD + ty * 4 + i] = s[i][j];
        __syncthreads();

#pragma unroll
        for (int kc = 0; kc < 64; kc++) {
            float a[4], bb[4];
            *(float4*)a  = *(const float4*)&Pst[kc * PAD + ty * 4];
            *(float4*)bb = *(const float4*)&Vs[kc * PAD + tx * 4];
#pragma unroll
            for (int i = 0; i < 4; i++)
#pragma unroll
                for (int j = 0; j < 4; j++)
                    o[i][j] = fmaf(a[i], bb[j], o[i][j]);
        }
    }

#pragma unroll
    for (int i = 0; i < 4; i++) {
        float inv = 1.0f / l_r[i];
        float4 ov = make_float4(o[i][0] * inv, o[i][1] * inv,
                                o[i][2] * inv, o[i][3] * inv);
        *(float4*)&ctx[((size_t)b * SEQLEN + q0 + ty * 4 + i) * D_MODEL + h * DK + tx * 4] = ov;
    }
}

// ---------------------------------------------------------------------------
// Launch
// ---------------------------------------------------------------------------
extern "C" void kernel_launch(void* const* d_in, const int* in_sizes, int n_in,
                              void* d_out, int out_size)
{
    (void)in_sizes; (void)n_in; (void)out_size;
    const float* q    = (const float*)d_in[0];
    const float* k    = (const float*)d_in[1];
    const float* v    = (const float*)d_in[2];
    const int*   mask = (const int*)d_in[3];
    const float* Wq   = (const float*)d_in[4];
    const float* bq   = (const float*)d_in[5];
    const float* Wk   = (const float*)d_in[6];
    const float* bk   = (const float*)d_in[7];
    const float* Wv   = (const float*)d_in[8];
    const float* bv   = (const float*)d_in[9];
    const float* Wo   = (const float*)d_in[10];
    const float* bo   = (const float*)d_in[11];
    float* out = (float*)d_out;

    float *qh, *kh, *vh, *ctx;
    unsigned short *ah, *al, *bth, *btl;
    cudaGetSymbolAddress((void**)&qh,  g_qh);
    cudaGetSymbolAddress((void**)&kh,  g_kh);
    cudaGetSymbolAddress((void**)&vh,  g_vh);
    cudaGetSymbolAddress((void**)&ctx, g_ctx);
    cudaGetSymbolAddress((void**)&ah,  g_ah);
    cudaGetSymbolAddress((void**)&al,  g_al);
    cudaGetSymbolAddress((void**)&bth, g_bth);
    cudaGetSymbolAddress((void**)&btl, g_btl);

    static bool attr_set = false;
    if (!attr_set) {
        cudaFuncSetAttribute(gemm_tc_kernel,
                             cudaFuncAttributeMaxDynamicSharedMemorySize, G_SMEM_TOTAL);
        cudaFuncSetAttribute(attn_kernel,
                             cudaFuncAttributeMaxDynamicSharedMemorySize,
                             4 * 64 * PAD * (int)sizeof(float));
        attr_set = true;
    }

    const int convA_blocks = (MTOT * D_MODEL / 4) / 256;   // 8192
    dim3 bt_grid(32, 32), bt_block(32, 8);
    dim3 gemm_grid(D_MODEL / 128, MTOT / 128);             // (8, 64)

    // Q projection
    conv_bt_kernel<<<bt_grid, bt_block>>>(Wq, bth, btl);
    conv_hilo_kernel<<<convA_blocks, 256>>>((const float4*)q, (uint2*)ah, (uint2*)al);
    gemm_tc_kernel<<<gemm_grid, 256, G_SMEM_TOTAL>>>(ah, al, bth, btl, bq, qh);
    // K projection
    conv_bt_kernel<<<bt_grid, bt_block>>>(Wk, bth, btl);
    conv_hilo_kernel<<<convA_blocks, 256>>>((const float4*)k, (uint2*)ah, (uint2*)al);
    gemm_tc_kernel<<<gemm_grid, 256, G_SMEM_TOTAL>>>(ah, al, bth, btl, bk, kh);
    // V projection
    conv_bt_kernel<<<bt_grid, bt_block>>>(Wv, bth, btl);
    conv_hilo_kernel<<<convA_blocks, 256>>>((const float4*)v, (uint2*)ah, (uint2*)al);
    gemm_tc_kernel<<<gemm_grid, 256, G_SMEM_TOTAL>>>(ah, al, bth, btl, bv, vh);

    // Attention
    const int attn_smem = 4 * 64 * PAD * (int)sizeof(float);
    dim3 attn_grid(SEQLEN / 64, HNUM, BSZ);
    attn_kernel<<<attn_grid, 256, attn_smem>>>(qh, kh, vh, mask, ctx);

    // Output projection
    conv_bt_kernel<<<bt_grid, bt_block>>>(Wo, bth, btl);
    conv_hilo_kernel<<<convA_blocks, 256>>>((const float4*)ctx, (uint2*)ah, (uint2*)al);
    gemm_tc_kernel<<<gemm_grid, 256, G_SMEM_TOTAL>>>(ah, al, bth, btl, bo, out);
}